// round 5
// baseline (speedup 1.0000x reference)
#include <cuda_runtime.h>
#include <cuda_fp16.h>
#include <math.h>

#define B_ 4
#define N_ 65536
#define K_ 16
#define D_ 8
#define EPS_ 1e-6f
#define SLOPE_ 0.2f

// 32B record per point: [x,y,z,pad (fp32) | f0..f7 (fp16)]
__device__ float4 g_rec[(size_t)B_ * N_ * 2];
__device__ float4 g_e[(size_t)B_ * N_ * 2];   // per-point e[8] = bias + A·ext
__device__ double g_sums[16];                 // sum_y[0..7], sum_y2[8..15]
__device__ float  g_wp[64];                   // [0..7]=W0, [8..31]=A, [32..55]=C, [56..63]=bias
__constant__ float c_wp[64];

// ---------------- Pass 0: pack records + per-point e[8]; block0 preps weights/stats ----------------
__global__ void __launch_bounds__(256) k0_pack(const float* __restrict__ coords,
                                               const float* __restrict__ feats,
                                               const float* __restrict__ conv_w,
                                               const float* __restrict__ conv_b) {
    __shared__ float sA[24], sb[8];
    if (threadIdx.x < 8) {
        int o = threadIdx.x;
        const float* w = conv_w + o * 10;
        float a0 = w[1] + w[4], a1 = w[2] + w[5], a2 = w[3] + w[6];
        sA[o * 3 + 0] = a0; sA[o * 3 + 1] = a1; sA[o * 3 + 2] = a2;
        sb[o] = conv_b[o];
        if (blockIdx.x == 0) {
            g_wp[o]      = w[0];
            g_wp[8 + o*3 + 0] = a0; g_wp[8 + o*3 + 1] = a1; g_wp[8 + o*3 + 2] = a2;
            g_wp[32 + o*3 + 0] = w[7] - w[1];
            g_wp[32 + o*3 + 1] = w[8] - w[2];
            g_wp[32 + o*3 + 2] = w[9] - w[3];
            g_wp[56 + o] = conv_b[o];
            g_sums[o] = 0.0; g_sums[8 + o] = 0.0;
        }
    }
    __syncthreads();

    int t = blockIdx.x * blockDim.x + threadIdx.x;
    if (t >= B_ * N_) return;
    int b = t >> 16;
    int n = t & (N_ - 1);
    float cx = coords[(size_t)t * 3 + 0];
    float cy = coords[(size_t)t * 3 + 1];
    float cz = coords[(size_t)t * 3 + 2];

    const float* fb = feats + (size_t)b * D_ * N_ + n;
    __half2 h01 = __floats2half2_rn(fb[0 * N_], fb[1 * N_]);
    __half2 h23 = __floats2half2_rn(fb[2 * N_], fb[3 * N_]);
    __half2 h45 = __floats2half2_rn(fb[4 * N_], fb[5 * N_]);
    __half2 h67 = __floats2half2_rn(fb[6 * N_], fb[7 * N_]);
    float4 hv;
    hv.x = __uint_as_float(*(const unsigned*)&h01);
    hv.y = __uint_as_float(*(const unsigned*)&h23);
    hv.z = __uint_as_float(*(const unsigned*)&h45);
    hv.w = __uint_as_float(*(const unsigned*)&h67);

    float4* r = &g_rec[(size_t)t * 2];
    r[0] = make_float4(cx, cy, cz, 0.f);
    r[1] = hv;

    float e[8];
    #pragma unroll
    for (int o = 0; o < 8; o++)
        e[o] = sb[o] + sA[o*3] * cx + sA[o*3+1] * cy + sA[o*3+2] * cz;
    g_e[(size_t)t * 2 + 0] = make_float4(e[0], e[1], e[2], e[3]);
    g_e[(size_t)t * 2 + 1] = make_float4(e[4], e[5], e[6], e[7]);
}

// ---------------- Pass 1: BN statistics (runs concurrent with k3a) ----------------
__global__ void __launch_bounds__(256, 4) k1_stats(const int* __restrict__ idx) {
    int t = blockIdx.x * blockDim.x + threadIdx.x;   // one (b,n) per thread
    int base = (t >> 16) << 16;
    const float4* rec = g_rec;
    float4 ext = rec[(size_t)t * 2];

    float4 e01 = g_e[(size_t)t * 2 + 0];
    float4 e23 = g_e[(size_t)t * 2 + 1];
    float e[8] = {e01.x, e01.y, e01.z, e01.w, e23.x, e23.y, e23.z, e23.w};

    float sy[8], sy2[8];
    #pragma unroll
    for (int o = 0; o < 8; o++) { sy[o] = 0.f; sy2[o] = 0.f; }

    const int4* ip = (const int4*)idx + (size_t)t * 4;
    #pragma unroll
    for (int kk = 0; kk < 4; kk++) {
        int4 j4 = ip[kk];
        int js[4] = {j4.x, j4.y, j4.z, j4.w};
        #pragma unroll
        for (int u = 0; u < 4; u++) {
            float4 nb = rec[(size_t)(base + js[u]) * 2];
            float rx = ext.x - nb.x, ry = ext.y - nb.y, rz = ext.z - nb.z;
            float d = sqrtf(rx * rx + ry * ry + rz * rz);
            #pragma unroll
            for (int o = 0; o < 8; o++) {
                float y = e[o] + c_wp[o] * d + c_wp[32 + o*3] * nb.x
                        + c_wp[33 + o*3] * nb.y + c_wp[34 + o*3] * nb.z;
                sy[o]  += y;
                sy2[o] += y * y;
            }
        }
    }

    #pragma unroll
    for (int o = 0; o < 8; o++) {
        #pragma unroll
        for (int off = 16; off > 0; off >>= 1) {
            sy[o]  += __shfl_down_sync(0xffffffffu, sy[o],  off);
            sy2[o] += __shfl_down_sync(0xffffffffu, sy2[o], off);
        }
    }
    __shared__ float ps[16];
    if (threadIdx.x < 16) ps[threadIdx.x] = 0.f;
    __syncthreads();
    if ((threadIdx.x & 31) == 0) {
        #pragma unroll
        for (int o = 0; o < 8; o++) {
            atomicAdd(&ps[o],     sy[o]);
            atomicAdd(&ps[8 + o], sy2[o]);
        }
    }
    __syncthreads();
    if (threadIdx.x < 16) atomicAdd(&g_sums[threadIdx.x], (double)ps[threadIdx.x]);
}

// ---------------- Pass 2a: neighbour-feature channels (no BN dependency) ----------------
__global__ void __launch_bounds__(256, 5) k3a_nf(const int* __restrict__ idx,
                                                 float* __restrict__ out) {
    int t  = blockIdx.x * blockDim.x + threadIdx.x;  // [0, B*N*K)
    int pn = t >> 4;
    int b  = pn >> 16;

    int j = __ldg(idx + t);
    float4 hf = g_rec[(((size_t)((b << 16) | j)) << 1) + 1];

    unsigned u0 = __float_as_uint(hf.x), u1 = __float_as_uint(hf.y);
    unsigned u2 = __float_as_uint(hf.z), u3 = __float_as_uint(hf.w);
    float2 f01 = __half22float2(*(__half2*)&u0);
    float2 f23 = __half22float2(*(__half2*)&u1);
    float2 f45 = __half22float2(*(__half2*)&u2);
    float2 f67 = __half22float2(*(__half2*)&u3);

    const size_t plane = (size_t)N_ * K_;
    size_t inner = (size_t)(t & (int)(plane - 1));
    float* o1 = out + (size_t)b * 16 * plane + inner;   // (B,16,N,K) channels 0..7

    o1[0 * plane] = f01.x; o1[1 * plane] = f01.y;
    o1[2 * plane] = f23.x; o1[3 * plane] = f23.y;
    o1[4 * plane] = f45.x; o1[5 * plane] = f45.y;
    o1[6 * plane] = f67.x; o1[7 * plane] = f67.y;
}

// ---------------- Pass 2b: y channels (BN finalize per block + LeakyReLU) ----------------
__global__ void __launch_bounds__(256, 5) k3b_y(const int* __restrict__ idx,
                                                const float* __restrict__ gamma,
                                                const float* __restrict__ beta,
                                                float* __restrict__ out) {
    __shared__ float s_bn[16];    // scale[0..7], shift[8..15]
    if (threadIdx.x < 8) {
        int o = threadIdx.x;
        double M    = (double)B_ * N_ * K_;
        double mean = g_sums[o] / M;
        double var  = g_sums[8 + o] / M - mean * mean;
        float  sc   = (float)((double)gamma[o] / sqrt(var + (double)EPS_));
        s_bn[o]     = sc;
        s_bn[8 + o] = beta[o] - (float)mean * sc;
    }
    __syncthreads();

    int t  = blockIdx.x * blockDim.x + threadIdx.x;  // [0, B*N*K)
    int pn = t >> 4;
    int b  = pn >> 16;

    int j = __ldg(idx + t);
    float4 nb = g_rec[((size_t)((b << 16) | j)) << 1];

    float4 ext = g_rec[(size_t)pn << 1];
    float rx = ext.x - nb.x, ry = ext.y - nb.y, rz = ext.z - nb.z;
    float d = sqrtf(rx * rx + ry * ry + rz * rz);

    float4 e01 = g_e[(size_t)pn * 2 + 0];
    float4 e23 = g_e[(size_t)pn * 2 + 1];
    float e[8] = {e01.x, e01.y, e01.z, e01.w, e23.x, e23.y, e23.z, e23.w};

    const size_t plane = (size_t)N_ * K_;
    size_t inner = (size_t)(t & (int)(plane - 1));
    float* o1 = out + (size_t)b * 16 * plane + inner;                          // channels 8..15
    float* o2 = out + (size_t)B_ * 16 * plane + (size_t)b * 8 * plane + inner; // (B,8,N,K)

    #pragma unroll
    for (int o = 0; o < 8; o++) {
        float y = e[o] + c_wp[o] * d + c_wp[32 + o*3] * nb.x
                + c_wp[33 + o*3] * nb.y + c_wp[34 + o*3] * nb.z;
        float z = fmaf(y, s_bn[o], s_bn[8 + o]);
        z = fmaxf(z, SLOPE_ * z);
        o1[(size_t)(8 + o) * plane] = z;
        o2[(size_t)o * plane]       = z;
    }
}

extern "C" void kernel_launch(void* const* d_in, const int* in_sizes, int n_in,
                              void* d_out, int out_size) {
    const float* coords = (const float*)d_in[0];
    const float* feats  = (const float*)d_in[1];
    const int*   idx    = (const int*)d_in[2];
    const float* conv_w = (const float*)d_in[3];
    const float* conv_b = (const float*)d_in[4];
    const float* gamma  = (const float*)d_in[5];
    const float* beta   = (const float*)d_in[6];
    float* out = (float*)d_out;

    // lazily-created side stream + events (host objects only; same work every call)
    static cudaStream_t s1 = nullptr;
    static cudaEvent_t ev_fork = nullptr, ev_join = nullptr;
    if (s1 == nullptr) {
        cudaStreamCreateWithFlags(&s1, cudaStreamNonBlocking);
        cudaEventCreateWithFlags(&ev_fork, cudaEventDisableTiming);
        cudaEventCreateWithFlags(&ev_join, cudaEventDisableTiming);
    }

    void *c_wp_p = nullptr, *g_wp_p = nullptr;
    cudaGetSymbolAddress(&c_wp_p, c_wp);
    cudaGetSymbolAddress(&g_wp_p, g_wp);

    cudaStream_t s0 = 0;

    k0_pack<<<(B_ * N_ + 255) / 256, 256, 0, s0>>>(coords, feats, conv_w, conv_b);
    cudaMemcpyAsync(c_wp_p, g_wp_p, 64 * sizeof(float), cudaMemcpyDeviceToDevice, s0);

    // fork: k3a (nf channels, DRAM-bound) runs concurrent with k1 (L2-gather-bound)
    cudaEventRecord(ev_fork, s0);
    cudaStreamWaitEvent(s1, ev_fork, 0);
    k3a_nf<<<(B_ * N_ * K_) / 256, 256, 0, s1>>>(idx, out);
    k1_stats<<<(B_ * N_) / 256, 256, 0, s0>>>(idx);
    // join
    cudaEventRecord(ev_join, s1);
    cudaStreamWaitEvent(s0, ev_join, 0);

    k3b_y<<<(B_ * N_ * K_) / 256, 256, 0, s0>>>(idx, gamma, beta, out);
}

// round 6
// speedup vs baseline: 1.1761x; 1.1761x over previous
#include <cuda_runtime.h>
#include <cuda_fp16.h>
#include <math.h>

#define B_ 4
#define N_ 65536
#define K_ 16
#define D_ 8
#define EPS_ 1e-6f
#define SLOPE_ 0.2f

// 32B record per point: [x,y,z,pad (fp32) | f0..f7 (fp16)]
__device__ float4 g_rec[(size_t)B_ * N_ * 2];
__device__ float4 g_e[(size_t)B_ * N_ * 2];   // per-point e[8] = bias + A·ext
__device__ double g_sums[16];                 // sum_y[0..7], sum_y2[8..15]
__device__ float  g_wp[64];                   // [0..7]=W0, [8..31]=A, [32..55]=C, [56..63]=bias
__constant__ float c_wp[64];

// ---------------- Pass 0: pack records + per-point e[8]; 4 points per thread ----------------
__global__ void __launch_bounds__(256) k0_pack(const float* __restrict__ coords,
                                               const float* __restrict__ feats,
                                               const float* __restrict__ conv_w,
                                               const float* __restrict__ conv_b) {
    __shared__ float sA[24], sb[8];
    if (threadIdx.x < 8) {
        int o = threadIdx.x;
        const float* w = conv_w + o * 10;
        float a0 = w[1] + w[4], a1 = w[2] + w[5], a2 = w[3] + w[6];
        sA[o * 3 + 0] = a0; sA[o * 3 + 1] = a1; sA[o * 3 + 2] = a2;
        sb[o] = conv_b[o];
        if (blockIdx.x == 0) {
            g_wp[o]      = w[0];
            g_wp[8 + o*3 + 0] = a0; g_wp[8 + o*3 + 1] = a1; g_wp[8 + o*3 + 2] = a2;
            g_wp[32 + o*3 + 0] = w[7] - w[1];
            g_wp[32 + o*3 + 1] = w[8] - w[2];
            g_wp[32 + o*3 + 2] = w[9] - w[3];
            g_wp[56 + o] = conv_b[o];
            g_sums[o] = 0.0; g_sums[8 + o] = 0.0;
        }
    }
    __syncthreads();

    int t  = blockIdx.x * blockDim.x + threadIdx.x;   // handles points 4t..4t+3
    int p0 = t * 4;
    if (p0 >= B_ * N_) return;
    int b  = p0 >> 16;
    int n0 = p0 & (N_ - 1);

    // coords: 12 consecutive floats = 3 float4 loads
    const float4* cp = (const float4*)(coords + (size_t)p0 * 3);
    float4 ca = cp[0], cb4 = cp[1], cc = cp[2];
    float cxs[4] = {ca.x, ca.w, cb4.z, cc.y};
    float cys[4] = {ca.y, cb4.x, cb4.w, cc.z};
    float czs[4] = {ca.z, cb4.y, cc.x, cc.w};

    // feats: 8 channels, float4 (4 consecutive n) per channel
    const float* fb = feats + (size_t)b * D_ * N_ + n0;
    float4 fc[8];
    #pragma unroll
    for (int c = 0; c < 8; c++) fc[c] = *(const float4*)(fb + (size_t)c * N_);

    #pragma unroll
    for (int u = 0; u < 4; u++) {
        float fv[4] = { ((const float*)&fc[0])[u], ((const float*)&fc[1])[u],
                        ((const float*)&fc[2])[u], ((const float*)&fc[3])[u] };
        float fw[4] = { ((const float*)&fc[4])[u], ((const float*)&fc[5])[u],
                        ((const float*)&fc[6])[u], ((const float*)&fc[7])[u] };
        __half2 h01 = __floats2half2_rn(fv[0], fv[1]);
        __half2 h23 = __floats2half2_rn(fv[2], fv[3]);
        __half2 h45 = __floats2half2_rn(fw[0], fw[1]);
        __half2 h67 = __floats2half2_rn(fw[2], fw[3]);
        float4 hv;
        hv.x = __uint_as_float(*(const unsigned*)&h01);
        hv.y = __uint_as_float(*(const unsigned*)&h23);
        hv.z = __uint_as_float(*(const unsigned*)&h45);
        hv.w = __uint_as_float(*(const unsigned*)&h67);

        float4* r = &g_rec[(size_t)(p0 + u) * 2];
        r[0] = make_float4(cxs[u], cys[u], czs[u], 0.f);
        r[1] = hv;

        float e[8];
        #pragma unroll
        for (int o = 0; o < 8; o++)
            e[o] = sb[o] + sA[o*3] * cxs[u] + sA[o*3+1] * cys[u] + sA[o*3+2] * czs[u];
        g_e[(size_t)(p0 + u) * 2 + 0] = make_float4(e[0], e[1], e[2], e[3]);
        g_e[(size_t)(p0 + u) * 2 + 1] = make_float4(e[4], e[5], e[6], e[7]);
    }
}

// ---------------- Pass 1: BN statistics ----------------
__global__ void __launch_bounds__(256, 6) k1_stats(const int* __restrict__ idx) {
    int t = blockIdx.x * blockDim.x + threadIdx.x;   // one (b,n) per thread
    int base = (t >> 16) << 16;
    const float4* rec = g_rec;
    float4 ext = rec[(size_t)t * 2];

    float4 e01 = g_e[(size_t)t * 2 + 0];
    float4 e23 = g_e[(size_t)t * 2 + 1];
    float e[8] = {e01.x, e01.y, e01.z, e01.w, e23.x, e23.y, e23.z, e23.w};

    float sy[8], sy2[8];
    #pragma unroll
    for (int o = 0; o < 8; o++) { sy[o] = 0.f; sy2[o] = 0.f; }

    const int4* ip = (const int4*)idx + (size_t)t * 4;
    #pragma unroll
    for (int kk = 0; kk < 4; kk++) {
        int4 j4 = ip[kk];
        int js[4] = {j4.x, j4.y, j4.z, j4.w};
        #pragma unroll
        for (int u = 0; u < 4; u++) {
            float4 nb = rec[(size_t)(base + js[u]) * 2];
            float rx = ext.x - nb.x, ry = ext.y - nb.y, rz = ext.z - nb.z;
            float d = sqrtf(rx * rx + ry * ry + rz * rz);
            #pragma unroll
            for (int o = 0; o < 8; o++) {
                float y = e[o] + c_wp[o] * d + c_wp[32 + o*3] * nb.x
                        + c_wp[33 + o*3] * nb.y + c_wp[34 + o*3] * nb.z;
                sy[o]  += y;
                sy2[o] += y * y;
            }
        }
    }

    #pragma unroll
    for (int o = 0; o < 8; o++) {
        #pragma unroll
        for (int off = 16; off > 0; off >>= 1) {
            sy[o]  += __shfl_down_sync(0xffffffffu, sy[o],  off);
            sy2[o] += __shfl_down_sync(0xffffffffu, sy2[o], off);
        }
    }
    __shared__ float ps[16];
    if (threadIdx.x < 16) ps[threadIdx.x] = 0.f;
    __syncthreads();
    if ((threadIdx.x & 31) == 0) {
        #pragma unroll
        for (int o = 0; o < 8; o++) {
            atomicAdd(&ps[o],     sy[o]);
            atomicAdd(&ps[8 + o], sy2[o]);
        }
    }
    __syncthreads();
    if (threadIdx.x < 16) atomicAdd(&g_sums[threadIdx.x], (double)ps[threadIdx.x]);
}

// ---------------- Pass 2: one thread per neighbour; BN finalize per block ----------------
__global__ void __launch_bounds__(256, 6) k3_out(const int* __restrict__ idx,
                                                 const float* __restrict__ gamma,
                                                 const float* __restrict__ beta,
                                                 float* __restrict__ out) {
    __shared__ float s_bn[16];    // scale[0..7], shift[8..15]
    if (threadIdx.x < 8) {
        int o = threadIdx.x;
        double M    = (double)B_ * N_ * K_;
        double mean = g_sums[o] / M;
        double var  = g_sums[8 + o] / M - mean * mean;
        float  sc   = (float)((double)gamma[o] / sqrt(var + (double)EPS_));
        s_bn[o]     = sc;
        s_bn[8 + o] = beta[o] - (float)mean * sc;
    }
    __syncthreads();

    int t  = blockIdx.x * blockDim.x + threadIdx.x;  // [0, B*N*K)
    int pn = t >> 4;               // b*N + n
    int b  = pn >> 16;

    int j = __ldg(idx + t);
    const float4* rp = g_rec + ((size_t)((b << 16) | j) << 1);
    float4 nb = rp[0];
    float4 hf = rp[1];

    float4 ext = g_rec[(size_t)pn << 1];            // broadcast within warp
    float rx = ext.x - nb.x, ry = ext.y - nb.y, rz = ext.z - nb.z;
    float d = sqrtf(rx * rx + ry * ry + rz * rz);

    float4 e01 = g_e[(size_t)pn * 2 + 0];
    float4 e23 = g_e[(size_t)pn * 2 + 1];
    float e[8] = {e01.x, e01.y, e01.z, e01.w, e23.x, e23.y, e23.z, e23.w};

    // unpack fp16 features
    unsigned u0 = __float_as_uint(hf.x), u1 = __float_as_uint(hf.y);
    unsigned u2 = __float_as_uint(hf.z), u3 = __float_as_uint(hf.w);
    float2 f01 = __half22float2(*(__half2*)&u0);
    float2 f23 = __half22float2(*(__half2*)&u1);
    float2 f45 = __half22float2(*(__half2*)&u2);
    float2 f67 = __half22float2(*(__half2*)&u3);

    const size_t plane = (size_t)N_ * K_;           // 1,048,576
    size_t inner = (size_t)(t & (int)(plane - 1));  // n*K + k
    float* o1 = out + (size_t)b * 16 * plane + inner;                          // (B,16,N,K)
    float* o2 = out + (size_t)B_ * 16 * plane + (size_t)b * 8 * plane + inner; // (B,8,N,K)

    // neighbour-feature channels 0..7 (coalesced, streaming)
    __stcs(o1 + 0 * plane, f01.x); __stcs(o1 + 1 * plane, f01.y);
    __stcs(o1 + 2 * plane, f23.x); __stcs(o1 + 3 * plane, f23.y);
    __stcs(o1 + 4 * plane, f45.x); __stcs(o1 + 5 * plane, f45.y);
    __stcs(o1 + 6 * plane, f67.x); __stcs(o1 + 7 * plane, f67.y);

    // BN + LeakyReLU channels
    #pragma unroll
    for (int o = 0; o < 8; o++) {
        float y = e[o] + c_wp[o] * d + c_wp[32 + o*3] * nb.x
                + c_wp[33 + o*3] * nb.y + c_wp[34 + o*3] * nb.z;
        float z = fmaf(y, s_bn[o], s_bn[8 + o]);
        z = fmaxf(z, SLOPE_ * z);
        __stcs(o1 + (size_t)(8 + o) * plane, z);
        __stcs(o2 + (size_t)o * plane, z);
    }
}

extern "C" void kernel_launch(void* const* d_in, const int* in_sizes, int n_in,
                              void* d_out, int out_size) {
    const float* coords = (const float*)d_in[0];
    const float* feats  = (const float*)d_in[1];
    const int*   idx    = (const int*)d_in[2];
    const float* conv_w = (const float*)d_in[3];
    const float* conv_b = (const float*)d_in[4];
    const float* gamma  = (const float*)d_in[5];
    const float* beta   = (const float*)d_in[6];
    float* out = (float*)d_out;

    void *c_wp_p = nullptr, *g_wp_p = nullptr;
    cudaGetSymbolAddress(&c_wp_p, c_wp);
    cudaGetSymbolAddress(&g_wp_p, g_wp);

    k0_pack<<<(B_ * N_ / 4 + 255) / 256, 256>>>(coords, feats, conv_w, conv_b);
    cudaMemcpyAsync(c_wp_p, g_wp_p, 64 * sizeof(float), cudaMemcpyDeviceToDevice, 0);
    k1_stats<<<(B_ * N_) / 256, 256>>>(idx);
    k3_out<<<(B_ * N_ * K_) / 256, 256>>>(idx, gamma, beta, out);
}